// round 11
// baseline (speedup 1.0000x reference)
#include <cuda_runtime.h>
#include <math.h>

#define N_NODES 100000
#define N_EDGES 500000
#define HIDDEN  32
#define HEADS   4
#define PROJ    128
#define LN_EPS  1e-5f

// Folded parameters, produced once by precompute_kernel (1 block).
//   P[i][d], i = 4h+j: j=0..2 -> rel_j coefficient of (Wv_h @ Wout_h);
//                      j=3    -> bv_h @ Wout_h
//   Mas: M(36) = Wq_h Wk_h^T / sqrt(32), a(12), s(4) contiguous.
struct __align__(16) Params {
    float P[16][HIDDEN];   // 512 floats
    float Mas[52];
};
__device__ Params g_params;

// per-node reduced accumulator: z[n][i], i = 4h+j  (attn_h * {r0,r1,r2,1})
// Statically zero-initialized; node_kernel re-zeroes after consuming, so every
// graph replay starts from zeros without a dedicated zeroing launch.
__device__ __align__(16) float g_z[N_NODES * 16];

__device__ __forceinline__ void red_add_v4(float* addr, float x, float y, float z, float w) {
    asm volatile("red.global.add.v4.f32 [%0], {%1, %2, %3, %4};"
                 :: "l"(addr), "f"(x), "f"(y), "f"(z), "f"(w) : "memory");
}

// ---------------------------------------------------------------------------
// Kernel 0: fold weights. ONE block, 256 threads, all folds parallel:
//   t in [0,128): P columns      t in [128,164): M entries
//   t in [164,176): a entries    t in [176,180): s entries
// ---------------------------------------------------------------------------
__global__ void __launch_bounds__(256) precompute_kernel(
        const float* __restrict__ Wq, const float* __restrict__ bq,
        const float* __restrict__ Wk, const float* __restrict__ bk,
        const float* __restrict__ Wv, const float* __restrict__ bv,
        const float* __restrict__ Wout) {
    const int t = threadIdx.x;
    const float invs = rsqrtf((float)HIDDEN);

    if (t < 128) {
        const int h = t >> 5, d = t & 31;
        float p0 = 0.f, p1 = 0.f, p2 = 0.f, p3 = 0.f;
        #pragma unroll 8
        for (int m = 0; m < 32; m++) {
            const int pm = h * 32 + m;
            const float wo = __ldg(&Wout[pm * HIDDEN + d]);
            p0 = fmaf(__ldg(&Wv[0 * PROJ + pm]), wo, p0);
            p1 = fmaf(__ldg(&Wv[1 * PROJ + pm]), wo, p1);
            p2 = fmaf(__ldg(&Wv[2 * PROJ + pm]), wo, p2);
            p3 = fmaf(__ldg(&bv[pm]), wo, p3);
        }
        g_params.P[h * 4 + 0][d] = p0;
        g_params.P[h * 4 + 1][d] = p1;
        g_params.P[h * 4 + 2][d] = p2;
        g_params.P[h * 4 + 3][d] = p3;
    } else if (t < 164) {           // M[h][i*3+j]
        const int u = t - 128;
        const int h = u / 9, ij = u - h * 9, i = ij / 3, j = ij - i * 3;
        const float* qa = Wq + i * PROJ + h * 32;
        const float* kb = Wk + j * PROJ + h * 32;
        float acc = 0.f;
        #pragma unroll 8
        for (int m = 0; m < 32; m++) acc = fmaf(__ldg(&qa[m]), __ldg(&kb[m]), acc);
        g_params.Mas[u] = acc * invs;
    } else if (t < 176) {           // a[h][i]
        const int u = t - 164;
        const int h = u / 3, i = u - h * 3;
        const float* qa = Wq + i * PROJ + h * 32;
        const float* ka = Wk + i * PROJ + h * 32;
        float acc = 0.f;
        #pragma unroll 8
        for (int m = 0; m < 32; m++) {
            acc = fmaf(__ldg(&qa[m]), __ldg(&bk[h * 32 + m]), acc);
            acc = fmaf(__ldg(&ka[m]), __ldg(&bq[h * 32 + m]), acc);
        }
        g_params.Mas[36 + u] = acc * invs;
    } else if (t < 180) {           // s[h]
        const int h = t - 176;
        float acc = 0.f;
        #pragma unroll 8
        for (int m = 0; m < 32; m++)
            acc = fmaf(__ldg(&bq[h * 32 + m]), __ldg(&bk[h * 32 + m]), acc);
        g_params.Mas[48 + h] = acc * invs;
    }
}

// ---------------------------------------------------------------------------
// Kernel 1: per-edge score + softmax; scatter z = attn (x) (rel,1).
// 4 RED.128 per edge; no count atomic (sum_h attn_h == 1 encodes the count).
// edge_index is int32 (JAX x64-disabled demotes int64).
// ---------------------------------------------------------------------------
__global__ void __launch_bounds__(256) edge_kernel(const float* __restrict__ pos,
                                                   const int* __restrict__ ei) {
    __shared__ float sMas[52];
    if (threadIdx.x < 52) sMas[threadIdx.x] = g_params.Mas[threadIdx.x];
    __syncthreads();
    const float* sM = sMas;          // [h*9 + ..]
    const float* sA = sMas + 36;     // [h*3 + ..]
    const float* sS = sMas + 48;     // [h]

    const int e = blockIdx.x * blockDim.x + threadIdx.x;
    if (e >= N_EDGES) return;

    const int r = ei[e];
    const int c = ei[N_EDGES + e];

    const float r0 = __ldg(&pos[r * 3 + 0]) - __ldg(&pos[c * 3 + 0]);
    const float r1 = __ldg(&pos[r * 3 + 1]) - __ldg(&pos[c * 3 + 1]);
    const float r2 = __ldg(&pos[r * 3 + 2]) - __ldg(&pos[c * 3 + 2]);

    float sc[HEADS];
    #pragma unroll
    for (int h = 0; h < HEADS; h++) {
        const float* M = sM + h * 9;
        const float t0 = fmaf(M[0], r0, fmaf(M[1], r1, M[2] * r2));
        const float t1 = fmaf(M[3], r0, fmaf(M[4], r1, M[5] * r2));
        const float t2 = fmaf(M[6], r0, fmaf(M[7], r1, M[8] * r2));
        float s = fmaf(r0, t0, fmaf(r1, t1, r2 * t2));
        s = fmaf(sA[h * 3 + 0], r0, s);
        s = fmaf(sA[h * 3 + 1], r1, s);
        s = fmaf(sA[h * 3 + 2], r2, s);
        sc[h] = s + sS[h];
    }

    const float mx = fmaxf(fmaxf(sc[0], sc[1]), fmaxf(sc[2], sc[3]));
    float w[HEADS], sum = 0.f;
    #pragma unroll
    for (int h = 0; h < HEADS; h++) { w[h] = __expf(sc[h] - mx); sum += w[h]; }
    const float inv = 1.0f / sum;

    float* base = &g_z[(size_t)c * 16];
    #pragma unroll
    for (int h = 0; h < HEADS; h++) {
        const float wh = w[h] * inv;
        red_add_v4(base + 4 * h, wh * r0, wh * r1, wh * r2, wh);
    }
}

// ---------------------------------------------------------------------------
// Kernel 2: FOUR threads per node. Copies folded P from g_params into smem
// (cheap L2 hit), each quad thread computes 8 output channels, LN stats via
// 4 intra-quad shuffles. After reading z, the quad re-zeroes it in place.
// ---------------------------------------------------------------------------
__global__ void __launch_bounds__(256) node_kernel(const float* __restrict__ bout,
                                                   const float* __restrict__ gamma,
                                                   const float* __restrict__ beta,
                                                   float* __restrict__ out) {
    __shared__ float Ps[16][32];          // rows are 128B -> float4-aligned
    __shared__ float sb[32], sg[32], sbt[32];
    {
        const int t = threadIdx.x;
        if (t < 128) ((float4*)Ps)[t] = ((const float4*)g_params.P)[t];
        else if (t < 160) sb[t - 128]  = __ldg(&bout[t - 128]);
        else if (t < 192) sg[t - 160]  = __ldg(&gamma[t - 160]);
        else if (t < 224) sbt[t - 192] = __ldg(&beta[t - 192]);
    }
    __syncthreads();

    const int gt = blockIdx.x * blockDim.x + threadIdx.x;
    const int n = gt >> 2;          // node
    const int q = gt & 3;           // quad lane: channels [8q, 8q+8)
    if (n >= N_NODES) return;       // warp-uniform (400k = 12500 whole warps)

    float4* zp = (float4*)&g_z[(size_t)n * 16];
    const float4 z0 = zp[0], z1 = zp[1], z2 = zp[2], z3 = zp[3];
    // Re-zero for the next graph replay. Safe: the quad's loads above are
    // issued in warp lockstep before this store; no other warp touches node n.
    zp[q] = make_float4(0.f, 0.f, 0.f, 0.f);

    const float z[16] = { z0.x, z0.y, z0.z, z0.w,  z1.x, z1.y, z1.z, z1.w,
                          z2.x, z2.y, z2.z, z2.w,  z3.x, z3.y, z3.z, z3.w };

    // count = sum over edges of sum_h attn_h (== 1 per edge)
    const float cnt = fmaxf(rintf(z0.w + z1.w + z2.w + z3.w), 1.0f);
    const float icnt = 1.0f / cnt;

    // u = P^T z for my 8 channels (two float4 groups: 2q, 2q+1)
    float4 u0 = make_float4(0.f, 0.f, 0.f, 0.f);
    float4 u1 = make_float4(0.f, 0.f, 0.f, 0.f);
    #pragma unroll
    for (int i = 0; i < 16; i++) {
        const float zi = z[i];
        const float4 pa = ((const float4*)Ps[i])[2 * q];
        const float4 pb = ((const float4*)Ps[i])[2 * q + 1];
        u0.x = fmaf(zi, pa.x, u0.x); u0.y = fmaf(zi, pa.y, u0.y);
        u0.z = fmaf(zi, pa.z, u0.z); u0.w = fmaf(zi, pa.w, u0.w);
        u1.x = fmaf(zi, pb.x, u1.x); u1.y = fmaf(zi, pb.y, u1.y);
        u1.z = fmaf(zi, pb.z, u1.z); u1.w = fmaf(zi, pb.w, u1.w);
    }

    const int cbase = 8 * q;
    float x[8];
    x[0] = fmaf(u0.x, icnt, sb[cbase + 0]);
    x[1] = fmaf(u0.y, icnt, sb[cbase + 1]);
    x[2] = fmaf(u0.z, icnt, sb[cbase + 2]);
    x[3] = fmaf(u0.w, icnt, sb[cbase + 3]);
    x[4] = fmaf(u1.x, icnt, sb[cbase + 4]);
    x[5] = fmaf(u1.y, icnt, sb[cbase + 5]);
    x[6] = fmaf(u1.z, icnt, sb[cbase + 6]);
    x[7] = fmaf(u1.w, icnt, sb[cbase + 7]);

    float mu = 0.f;
    #pragma unroll
    for (int d = 0; d < 8; d++) mu += x[d];
    mu += __shfl_xor_sync(0xFFFFFFFFu, mu, 1);
    mu += __shfl_xor_sync(0xFFFFFFFFu, mu, 2);
    mu *= (1.0f / HIDDEN);

    float var = 0.f;
    #pragma unroll
    for (int d = 0; d < 8; d++) { const float dv = x[d] - mu; var += dv * dv; }
    var += __shfl_xor_sync(0xFFFFFFFFu, var, 1);
    var += __shfl_xor_sync(0xFFFFFFFFu, var, 2);
    var *= (1.0f / HIDDEN);
    const float rstd = rsqrtf(var + LN_EPS);

    float4 o0, o1;
    float y;
    y = (x[0] - mu) * rstd * sg[cbase + 0] + sbt[cbase + 0]; o0.x = y / (1.0f + __expf(-y));
    y = (x[1] - mu) * rstd * sg[cbase + 1] + sbt[cbase + 1]; o0.y = y / (1.0f + __expf(-y));
    y = (x[2] - mu) * rstd * sg[cbase + 2] + sbt[cbase + 2]; o0.z = y / (1.0f + __expf(-y));
    y = (x[3] - mu) * rstd * sg[cbase + 3] + sbt[cbase + 3]; o0.w = y / (1.0f + __expf(-y));
    y = (x[4] - mu) * rstd * sg[cbase + 4] + sbt[cbase + 4]; o1.x = y / (1.0f + __expf(-y));
    y = (x[5] - mu) * rstd * sg[cbase + 5] + sbt[cbase + 5]; o1.y = y / (1.0f + __expf(-y));
    y = (x[6] - mu) * rstd * sg[cbase + 6] + sbt[cbase + 6]; o1.z = y / (1.0f + __expf(-y));
    y = (x[7] - mu) * rstd * sg[cbase + 7] + sbt[cbase + 7]; o1.w = y / (1.0f + __expf(-y));

    float4* op = (float4*)&out[(size_t)n * 32 + cbase];
    op[0] = o0;
    op[1] = o1;
}

// ---------------------------------------------------------------------------
extern "C" void kernel_launch(void* const* d_in, const int* in_sizes, int n_in,
                              void* d_out, int out_size) {
    const float* positions = (const float*)d_in[0];
    const int*   edge_idx  = (const int*)d_in[1];    // int32
    const float* Wq   = (const float*)d_in[2];
    const float* bq   = (const float*)d_in[3];
    const float* Wk   = (const float*)d_in[4];
    const float* bk   = (const float*)d_in[5];
    const float* Wv   = (const float*)d_in[6];
    const float* bv   = (const float*)d_in[7];
    const float* Wout = (const float*)d_in[8];
    const float* bout = (const float*)d_in[9];
    const float* gamma = (const float*)d_in[10];
    const float* beta  = (const float*)d_in[11];
    float* out = (float*)d_out;

    precompute_kernel<<<1, 256>>>(Wq, bq, Wk, bk, Wv, bv, Wout);
    edge_kernel<<<(N_EDGES + 255) / 256, 256>>>(positions, edge_idx);
    node_kernel<<<(N_NODES * 4 + 255) / 256, 256>>>(bout, gamma, beta, out);
}

// round 14
// speedup vs baseline: 1.7832x; 1.7832x over previous
#include <cuda_runtime.h>
#include <math.h>

#define N_NODES 100000
#define N_EDGES 500000
#define HIDDEN  32
#define HEADS   4
#define PROJ    128
#define LN_EPS  1e-5f

// Folded parameters, produced by block 0 of init_kernel.
//   P[i][d], i = 4h+j: j=0..2 -> rel_j coefficient of (Wv_h @ Wout_h);
//                      j=3    -> bv_h @ Wout_h
//   Mas: M(36) = Wq_h Wk_h^T / sqrt(32), a(12), s(4) contiguous.
struct __align__(16) Params {
    float P[16][HIDDEN];   // 512 floats
    float Mas[52];
};
__device__ Params g_params;

// per-node reduced accumulator: z[n][i], i = 4h+j  (attn_h * {r0,r1,r2,1})
__device__ __align__(16) float g_z[N_NODES * 16];

__device__ __forceinline__ void red_add_v4(float* addr, float x, float y, float z, float w) {
    asm volatile("red.global.add.v4.f32 [%0], {%1, %2, %3, %4};"
                 :: "l"(addr), "f"(x), "f"(y), "f"(z), "f"(w) : "memory");
}

// ---------------------------------------------------------------------------
// Kernel 0: blocks 1..N zero g_z; block 0 folds ALL params with 256 parallel
// threads (one 32-length dot each; ~32 regs so zeroing occupancy is unharmed):
//   t in [0,128): P columns      t in [128,164): M entries
//   t in [164,176): a entries    t in [176,180): s entries
// ---------------------------------------------------------------------------
__global__ void __launch_bounds__(256) init_kernel(
        const float* __restrict__ Wq, const float* __restrict__ bq,
        const float* __restrict__ Wk, const float* __restrict__ bk,
        const float* __restrict__ Wv, const float* __restrict__ bv,
        const float* __restrict__ Wout) {
    if (blockIdx.x != 0) {
        const int i = (blockIdx.x - 1) * blockDim.x + threadIdx.x;
        if (i < N_NODES * 4) ((float4*)g_z)[i] = make_float4(0.f, 0.f, 0.f, 0.f);
        return;
    }

    const int t = threadIdx.x;
    const float invs = rsqrtf((float)HIDDEN);

    if (t < 128) {
        const int h = t >> 5, d = t & 31;
        float p0 = 0.f, p1 = 0.f, p2 = 0.f, p3 = 0.f;
        #pragma unroll 8
        for (int m = 0; m < 32; m++) {
            const int pm = h * 32 + m;
            const float wo = __ldg(&Wout[pm * HIDDEN + d]);
            p0 = fmaf(__ldg(&Wv[0 * PROJ + pm]), wo, p0);
            p1 = fmaf(__ldg(&Wv[1 * PROJ + pm]), wo, p1);
            p2 = fmaf(__ldg(&Wv[2 * PROJ + pm]), wo, p2);
            p3 = fmaf(__ldg(&bv[pm]), wo, p3);
        }
        g_params.P[h * 4 + 0][d] = p0;
        g_params.P[h * 4 + 1][d] = p1;
        g_params.P[h * 4 + 2][d] = p2;
        g_params.P[h * 4 + 3][d] = p3;
    } else if (t < 164) {           // M[h][i*3+j]
        const int u = t - 128;
        const int h = u / 9, ij = u - h * 9, i = ij / 3, j = ij - i * 3;
        const float* qa = Wq + i * PROJ + h * 32;
        const float* kb = Wk + j * PROJ + h * 32;
        float acc = 0.f;
        #pragma unroll 8
        for (int m = 0; m < 32; m++) acc = fmaf(__ldg(&qa[m]), __ldg(&kb[m]), acc);
        g_params.Mas[u] = acc * invs;
    } else if (t < 176) {           // a[h][i]
        const int u = t - 164;
        const int h = u / 3, i = u - h * 3;
        const float* qa = Wq + i * PROJ + h * 32;
        const float* ka = Wk + i * PROJ + h * 32;
        float acc = 0.f;
        #pragma unroll 8
        for (int m = 0; m < 32; m++) {
            acc = fmaf(__ldg(&qa[m]), __ldg(&bk[h * 32 + m]), acc);
            acc = fmaf(__ldg(&ka[m]), __ldg(&bq[h * 32 + m]), acc);
        }
        g_params.Mas[36 + u] = acc * invs;
    } else if (t < 180) {           // s[h]
        const int h = t - 176;
        float acc = 0.f;
        #pragma unroll 8
        for (int m = 0; m < 32; m++)
            acc = fmaf(__ldg(&bq[h * 32 + m]), __ldg(&bk[h * 32 + m]), acc);
        g_params.Mas[48 + h] = acc * invs;
    }
}

// ---------------------------------------------------------------------------
// Kernel 1: per-edge score + softmax; scatter z = attn (x) (rel,1).
// 4 RED.128 per edge; no count atomic (sum_h attn_h == 1 encodes the count).
// edge_index is int32 (JAX x64-disabled demotes int64).
// ---------------------------------------------------------------------------
__global__ void __launch_bounds__(256) edge_kernel(const float* __restrict__ pos,
                                                   const int* __restrict__ ei) {
    __shared__ float sMas[52];
    if (threadIdx.x < 52) sMas[threadIdx.x] = g_params.Mas[threadIdx.x];
    __syncthreads();
    const float* sM = sMas;          // [h*9 + ..]
    const float* sA = sMas + 36;     // [h*3 + ..]
    const float* sS = sMas + 48;     // [h]

    const int e = blockIdx.x * blockDim.x + threadIdx.x;
    if (e >= N_EDGES) return;

    const int r = ei[e];
    const int c = ei[N_EDGES + e];

    const float r0 = __ldg(&pos[r * 3 + 0]) - __ldg(&pos[c * 3 + 0]);
    const float r1 = __ldg(&pos[r * 3 + 1]) - __ldg(&pos[c * 3 + 1]);
    const float r2 = __ldg(&pos[r * 3 + 2]) - __ldg(&pos[c * 3 + 2]);

    float sc[HEADS];
    #pragma unroll
    for (int h = 0; h < HEADS; h++) {
        const float* M = sM + h * 9;
        const float t0 = fmaf(M[0], r0, fmaf(M[1], r1, M[2] * r2));
        const float t1 = fmaf(M[3], r0, fmaf(M[4], r1, M[5] * r2));
        const float t2 = fmaf(M[6], r0, fmaf(M[7], r1, M[8] * r2));
        float s = fmaf(r0, t0, fmaf(r1, t1, r2 * t2));
        s = fmaf(sA[h * 3 + 0], r0, s);
        s = fmaf(sA[h * 3 + 1], r1, s);
        s = fmaf(sA[h * 3 + 2], r2, s);
        sc[h] = s + sS[h];
    }

    const float mx = fmaxf(fmaxf(sc[0], sc[1]), fmaxf(sc[2], sc[3]));
    float w[HEADS], sum = 0.f;
    #pragma unroll
    for (int h = 0; h < HEADS; h++) { w[h] = __expf(sc[h] - mx); sum += w[h]; }
    const float inv = 1.0f / sum;

    float* base = &g_z[(size_t)c * 16];
    #pragma unroll
    for (int h = 0; h < HEADS; h++) {
        const float wh = w[h] * inv;
        red_add_v4(base + 4 * h, wh * r0, wh * r1, wh * r2, wh);
    }
}

// ---------------------------------------------------------------------------
// Kernel 2: FOUR threads per node. Copies folded P from g_params into smem,
// each quad thread computes 8 output channels, LN stats via 4 intra-quad
// shuffles. (No re-zero here; init_kernel owns zeroing.)
// ---------------------------------------------------------------------------
__global__ void __launch_bounds__(256) node_kernel(const float* __restrict__ bout,
                                                   const float* __restrict__ gamma,
                                                   const float* __restrict__ beta,
                                                   float* __restrict__ out) {
    __shared__ float Ps[16][32];          // rows are 128B -> float4-aligned
    __shared__ float sb[32], sg[32], sbt[32];
    {
        const int t = threadIdx.x;
        if (t < 128) ((float4*)Ps)[t] = ((const float4*)g_params.P)[t];
        else if (t < 160) sb[t - 128]  = __ldg(&bout[t - 128]);
        else if (t < 192) sg[t - 160]  = __ldg(&gamma[t - 160]);
        else if (t < 224) sbt[t - 192] = __ldg(&beta[t - 192]);
    }
    __syncthreads();

    const int gt = blockIdx.x * blockDim.x + threadIdx.x;
    const int n = gt >> 2;          // node
    const int q = gt & 3;           // quad lane: channels [8q, 8q+8)
    if (n >= N_NODES) return;       // warp-uniform (400k = 12500 whole warps)

    const float4* zp = (const float4*)&g_z[(size_t)n * 16];
    const float4 z0 = zp[0], z1 = zp[1], z2 = zp[2], z3 = zp[3];
    const float z[16] = { z0.x, z0.y, z0.z, z0.w,  z1.x, z1.y, z1.z, z1.w,
                          z2.x, z2.y, z2.z, z2.w,  z3.x, z3.y, z3.z, z3.w };

    // count = sum over edges of sum_h attn_h (== 1 per edge)
    const float cnt = fmaxf(rintf(z0.w + z1.w + z2.w + z3.w), 1.0f);
    const float icnt = 1.0f / cnt;

    // u = P^T z for my 8 channels (two float4 groups: 2q, 2q+1)
    float4 u0 = make_float4(0.f, 0.f, 0.f, 0.f);
    float4 u1 = make_float4(0.f, 0.f, 0.f, 0.f);
    #pragma unroll
    for (int i = 0; i < 16; i++) {
        const float zi = z[i];
        const float4 pa = ((const float4*)Ps[i])[2 * q];
        const float4 pb = ((const float4*)Ps[i])[2 * q + 1];
        u0.x = fmaf(zi, pa.x, u0.x); u0.y = fmaf(zi, pa.y, u0.y);
        u0.z = fmaf(zi, pa.z, u0.z); u0.w = fmaf(zi, pa.w, u0.w);
        u1.x = fmaf(zi, pb.x, u1.x); u1.y = fmaf(zi, pb.y, u1.y);
        u1.z = fmaf(zi, pb.z, u1.z); u1.w = fmaf(zi, pb.w, u1.w);
    }

    const int cbase = 8 * q;
    float x[8];
    x[0] = fmaf(u0.x, icnt, sb[cbase + 0]);
    x[1] = fmaf(u0.y, icnt, sb[cbase + 1]);
    x[2] = fmaf(u0.z, icnt, sb[cbase + 2]);
    x[3] = fmaf(u0.w, icnt, sb[cbase + 3]);
    x[4] = fmaf(u1.x, icnt, sb[cbase + 4]);
    x[5] = fmaf(u1.y, icnt, sb[cbase + 5]);
    x[6] = fmaf(u1.z, icnt, sb[cbase + 6]);
    x[7] = fmaf(u1.w, icnt, sb[cbase + 7]);

    float mu = 0.f;
    #pragma unroll
    for (int d = 0; d < 8; d++) mu += x[d];
    mu += __shfl_xor_sync(0xFFFFFFFFu, mu, 1);
    mu += __shfl_xor_sync(0xFFFFFFFFu, mu, 2);
    mu *= (1.0f / HIDDEN);

    float var = 0.f;
    #pragma unroll
    for (int d = 0; d < 8; d++) { const float dv = x[d] - mu; var += dv * dv; }
    var += __shfl_xor_sync(0xFFFFFFFFu, var, 1);
    var += __shfl_xor_sync(0xFFFFFFFFu, var, 2);
    var *= (1.0f / HIDDEN);
    const float rstd = rsqrtf(var + LN_EPS);

    float4 o0, o1;
    float y;
    y = (x[0] - mu) * rstd * sg[cbase + 0] + sbt[cbase + 0]; o0.x = y / (1.0f + __expf(-y));
    y = (x[1] - mu) * rstd * sg[cbase + 1] + sbt[cbase + 1]; o0.y = y / (1.0f + __expf(-y));
    y = (x[2] - mu) * rstd * sg[cbase + 2] + sbt[cbase + 2]; o0.z = y / (1.0f + __expf(-y));
    y = (x[3] - mu) * rstd * sg[cbase + 3] + sbt[cbase + 3]; o0.w = y / (1.0f + __expf(-y));
    y = (x[4] - mu) * rstd * sg[cbase + 4] + sbt[cbase + 4]; o1.x = y / (1.0f + __expf(-y));
    y = (x[5] - mu) * rstd * sg[cbase + 5] + sbt[cbase + 5]; o1.y = y / (1.0f + __expf(-y));
    y = (x[6] - mu) * rstd * sg[cbase + 6] + sbt[cbase + 6]; o1.z = y / (1.0f + __expf(-y));
    y = (x[7] - mu) * rstd * sg[cbase + 7] + sbt[cbase + 7]; o1.w = y / (1.0f + __expf(-y));

    float4* op = (float4*)&out[(size_t)n * 32 + cbase];
    op[0] = o0;
    op[1] = o1;
}

// ---------------------------------------------------------------------------
extern "C" void kernel_launch(void* const* d_in, const int* in_sizes, int n_in,
                              void* d_out, int out_size) {
    const float* positions = (const float*)d_in[0];
    const int*   edge_idx  = (const int*)d_in[1];    // int32
    const float* Wq   = (const float*)d_in[2];
    const float* bq   = (const float*)d_in[3];
    const float* Wk   = (const float*)d_in[4];
    const float* bk   = (const float*)d_in[5];
    const float* Wv   = (const float*)d_in[6];
    const float* bv   = (const float*)d_in[7];
    const float* Wout = (const float*)d_in[8];
    const float* bout = (const float*)d_in[9];
    const float* gamma = (const float*)d_in[10];
    const float* beta  = (const float*)d_in[11];
    float* out = (float*)d_out;

    const int zero_blocks = (N_NODES * 4 + 255) / 256;      // 1563
    init_kernel<<<zero_blocks + 1, 256>>>(Wq, bq, Wk, bk, Wv, bv, Wout);
    edge_kernel<<<(N_EDGES + 255) / 256, 256>>>(positions, edge_idx);
    node_kernel<<<(N_NODES * 4 + 255) / 256, 256>>>(bout, gamma, beta, out);
}